// round 15
// baseline (speedup 1.0000x reference)
#include <cuda_runtime.h>
#include <cstdint>
#include <cstddef>

#define NN  50000
#define NE  800000
#define CH  512
#define CH4 128   // CH/4 float4 per row
#define BM  32
#define BK  32

// ---------------- scratch (device globals) -----------------------------------
__device__ int   g_cnt[2][NN];
__device__ float g_dis[2][NN];
__device__ int   g_rowptr[2][NN + 1];
__device__ int   g_cursor[2][NN];
__device__ int   g_src[2][NE];
__device__ float g_wgt[2][NE];
__device__ __align__(16) float g_bufA[(size_t)NN * CH];
__device__ __align__(16) float g_bufB[(size_t)NN * CH];
__device__ __align__(16) float g_bufC[(size_t)NN * CH];

// ---------------- helpers -----------------------------------------------------
__device__ __forceinline__ uint32_t smem_u32(const void* p) {
    uint32_t a;
    asm("{ .reg .u64 t; cvta.to.shared.u64 t, %1; cvt.u32.u64 %0, t; }"
        : "=r"(a) : "l"(p));
    return a;
}
__device__ __forceinline__ void cpa16(uint32_t dst, const void* src) {
    asm volatile("cp.async.cg.shared.global [%0], [%1], 16;"
                 :: "r"(dst), "l"(src) : "memory");
}
__device__ __forceinline__ void cp_commit() {
    asm volatile("cp.async.commit_group;" ::: "memory");
}
template <int N>
__device__ __forceinline__ void cp_wait() {
    asm volatile("cp.async.wait_group %0;" :: "n"(N) : "memory");
}

// ---------------- graph preprocessing (both graphs per launch) ---------------
__global__ void count2_kernel(const int* __restrict__ e1,
                              const int* __restrict__ e2) {
    int g = blockIdx.y;
    const int* ei = g ? e2 : e1;
    int e = blockIdx.x * blockDim.x + threadIdx.x;
    if (e < NE) {
        int c = ei[NE + e];
        if ((unsigned)c < (unsigned)NN) atomicAdd(&g_cnt[g][c], 1);
    }
}

// block g: dis + exclusive scan of counts (warp-shuffle scan)
__global__ void scandis_kernel() {
    int g = blockIdx.x;
    __shared__ int sw[32];
    __shared__ int s_carry;
    int t = threadIdx.x, l = t & 31, w = t >> 5;
    const unsigned full = 0xffffffffu;
    if (t == 0) s_carry = 0;
    __syncthreads();
    for (int base = 0; base < NN; base += 1024) {
        int i = base + t;
        int v = (i < NN) ? g_cnt[g][i] : 0;
        if (i < NN) g_dis[g][i] = rsqrtf((float)v + 1.0f);  // +1 self loop
        int incl = v;
#pragma unroll
        for (int o = 1; o < 32; o <<= 1) {
            int u = __shfl_up_sync(full, incl, o);
            if (l >= o) incl += u;
        }
        if (l == 31) sw[w] = incl;
        __syncthreads();
        if (w == 0) {
            int s = sw[l];
#pragma unroll
            for (int o = 1; o < 32; o <<= 1) {
                int u = __shfl_up_sync(full, s, o);
                if (l >= o) s += u;
            }
            sw[l] = s;
        }
        __syncthreads();
        int woff = w ? sw[w - 1] : 0;
        int excl = s_carry + woff + incl - v;
        if (i < NN) {
            g_rowptr[g][i] = excl;
            g_cursor[g][i] = excl;
        }
        __syncthreads();
        if (t == 1023) s_carry += sw[31];
        __syncthreads();
    }
    if (t == 0) g_rowptr[g][NN] = s_carry;
}

__global__ void scatter2_kernel(const int* __restrict__ e1,
                                const int* __restrict__ e2) {
    int g = blockIdx.y;
    const int* ei = g ? e2 : e1;
    int e = blockIdx.x * blockDim.x + threadIdx.x;
    if (e < NE) {
        int r = ei[e];
        int c = ei[NE + e];
        if ((unsigned)r < (unsigned)NN && (unsigned)c < (unsigned)NN) {
            int pos = atomicAdd(&g_cursor[g][c], 1);
            g_src[g][pos] = r;
            g_wgt[g][pos] = g_dis[g][r] * g_dis[g][c];
        }
    }
}

// ---------------- SpMM: gather-CSR, unroll x8 (R12-proven) -------------------
__global__ __launch_bounds__(128) void spmm_kernel(
    int g, const float4* __restrict__ in, float4* __restrict__ out) {
    int i = blockIdx.x, t = threadIdx.x;  // thread owns 4 channels of row i
    const int*   __restrict__ src = g_src[g];
    const float* __restrict__ wgt = g_wgt[g];
    float di = g_dis[g][i];
    int beg = g_rowptr[g][i], end = g_rowptr[g][i + 1];
    float4 h = in[(size_t)i * CH4 + t];
    float ws = di * di;  // self loop weight
    float4 a0 = make_float4(h.x * ws, h.y * ws, h.z * ws, h.w * ws);
    float4 a1 = make_float4(0, 0, 0, 0);
    float4 a2 = make_float4(0, 0, 0, 0);
    float4 a3 = make_float4(0, 0, 0, 0);
    int j = beg;
    int jal = (beg + 3) & ~3;   // align to 4-edge boundary for 16B vector loads
    if (jal > end) jal = end;
    for (; j < jal; ++j) {
        int s = __ldcs(&src[j]);
        float w = __ldcs(&wgt[j]);
        float4 v = in[(size_t)s * CH4 + t];
        a0.x = fmaf(w, v.x, a0.x); a0.y = fmaf(w, v.y, a0.y);
        a0.z = fmaf(w, v.z, a0.z); a0.w = fmaf(w, v.w, a0.w);
    }
    for (; j + 8 <= end; j += 8) {
        int4 sA = __ldcs((const int4*)&src[j]);
        int4 sB = __ldcs((const int4*)&src[j + 4]);
        float4 wA = __ldcs((const float4*)&wgt[j]);
        float4 wB = __ldcs((const float4*)&wgt[j + 4]);
        float4 v0 = in[(size_t)sA.x * CH4 + t];
        float4 v1 = in[(size_t)sA.y * CH4 + t];
        float4 v2 = in[(size_t)sA.z * CH4 + t];
        float4 v3 = in[(size_t)sA.w * CH4 + t];
        float4 v4 = in[(size_t)sB.x * CH4 + t];
        float4 v5 = in[(size_t)sB.y * CH4 + t];
        float4 v6 = in[(size_t)sB.z * CH4 + t];
        float4 v7 = in[(size_t)sB.w * CH4 + t];
        a0.x = fmaf(wA.x, v0.x, a0.x); a0.y = fmaf(wA.x, v0.y, a0.y);
        a0.z = fmaf(wA.x, v0.z, a0.z); a0.w = fmaf(wA.x, v0.w, a0.w);
        a1.x = fmaf(wA.y, v1.x, a1.x); a1.y = fmaf(wA.y, v1.y, a1.y);
        a1.z = fmaf(wA.y, v1.z, a1.z); a1.w = fmaf(wA.y, v1.w, a1.w);
        a2.x = fmaf(wA.z, v2.x, a2.x); a2.y = fmaf(wA.z, v2.y, a2.y);
        a2.z = fmaf(wA.z, v2.z, a2.z); a2.w = fmaf(wA.z, v2.w, a2.w);
        a3.x = fmaf(wA.w, v3.x, a3.x); a3.y = fmaf(wA.w, v3.y, a3.y);
        a3.z = fmaf(wA.w, v3.z, a3.z); a3.w = fmaf(wA.w, v3.w, a3.w);
        a0.x = fmaf(wB.x, v4.x, a0.x); a0.y = fmaf(wB.x, v4.y, a0.y);
        a0.z = fmaf(wB.x, v4.z, a0.z); a0.w = fmaf(wB.x, v4.w, a0.w);
        a1.x = fmaf(wB.y, v5.x, a1.x); a1.y = fmaf(wB.y, v5.y, a1.y);
        a1.z = fmaf(wB.y, v5.z, a1.z); a1.w = fmaf(wB.y, v5.w, a1.w);
        a2.x = fmaf(wB.z, v6.x, a2.x); a2.y = fmaf(wB.z, v6.y, a2.y);
        a2.z = fmaf(wB.z, v6.z, a2.z); a2.w = fmaf(wB.z, v6.w, a2.w);
        a3.x = fmaf(wB.w, v7.x, a3.x); a3.y = fmaf(wB.w, v7.y, a3.y);
        a3.z = fmaf(wB.w, v7.z, a3.z); a3.w = fmaf(wB.w, v7.w, a3.w);
    }
    for (; j < end; ++j) {
        int s = __ldcs(&src[j]);
        float w = __ldcs(&wgt[j]);
        float4 v = in[(size_t)s * CH4 + t];
        a0.x = fmaf(w, v.x, a0.x); a0.y = fmaf(w, v.y, a0.y);
        a0.z = fmaf(w, v.z, a0.z); a0.w = fmaf(w, v.w, a0.w);
    }
    float4 acc = make_float4((a0.x + a1.x) + (a2.x + a3.x),
                             (a0.y + a1.y) + (a2.y + a3.y),
                             (a0.z + a1.z) + (a2.z + a3.z),
                             (a0.w + a1.w) + (a2.w + a3.w));
    out[(size_t)i * CH4 + t] = acc;
}

// ---------------- fused GEMM (f32x2, double-buffered, BK=32) -----------------
// 256 threads, BM=32; dynamic smem 148.5KB (1 CTA/SM), 16 chunks = 16 syncs.
#define FMA2(d, a, b) \
    asm("fma.rn.f32x2 %0, %1, %2, %0;" : "+l"(d) : "l"(a), "l"(b))
#define AV(r, j) av[(r)][(j)]

#define SHW_BYTES (2 * BK * CH * 4)          // 131072
#define SHH_BYTES (2 * BK * (BM + 2) * 8)    // 17408
#define DSMEM (SHW_BYTES + SHH_BYTES)        // 148480

__global__ __launch_bounds__(256) void gemm_softmax_kernel(
    const float* __restrict__ Hm, const float* __restrict__ Wm,
    const float* __restrict__ Bv, float* __restrict__ out,
    float* __restrict__ pred, float* __restrict__ outbase, size_t out_lim) {
    extern __shared__ __align__(16) unsigned char smem[];
    __shared__ float rowmax[BM];
    __shared__ float rowinv[BM];
    __shared__ int   rowarg[BM];

    float (*shW)[BK][CH] = (float(*)[BK][CH])smem;                  // [2][32][512]
    unsigned long long (*shH)[BK][BM + 2] =
        (unsigned long long(*)[BK][BM + 2])(smem + SHW_BYTES);      // [2][32][34]
    float (*red)[65]  = (float(*)[65])smem;                         // overlay
    int   (*redi)[65] = (int(*)[65])(smem + 16640);

    int tid = threadIdx.x;
    int cg = tid & 63;          // 8-column group
    int rg = tid >> 6;          // 0..3: 8-row group
    int row0 = blockIdx.x * BM;

    unsigned long long acc[8][4];
#pragma unroll
    for (int r = 0; r < 8; ++r)
#pragma unroll
        for (int p = 0; p < 4; ++p) acc[r][p] = 0ULL;

    int hrow = tid >> 3;        // 0..31
    int hkk  = tid & 7;         // thread writes k = hkk + 8q, q = 0..3
    int hgr  = row0 + hrow;
    bool hvalid = (hgr < NN);
    const float* hptr = &Hm[(size_t)(hvalid ? hgr : 0) * CH + hkk];

    // W-tile cp.async: 16 x 16B per thread covers 32x512 floats
#pragma unroll
    for (int i = 0; i < 16; ++i) {
        int idx = tid + i * 256;
        int kr = idx >> 7, c4 = (idx & 127) << 2;
        cpa16(smem_u32(&shW[0][kr][c4]), &Wm[(size_t)kr * CH + c4]);
    }
    cp_commit();
    {
#pragma unroll
        for (int q = 0; q < 4; ++q) {
            float v = hvalid ? hptr[8 * q] : 0.0f;
            unsigned long long d = (unsigned long long)__float_as_uint(v);
            shH[0][hkk + 8 * q][hrow] = d | (d << 32);
        }
    }
    float hn[4];
#pragma unroll
    for (int q = 0; q < 4; ++q) hn[q] = hvalid ? hptr[BK + 8 * q] : 0.0f;
    cp_wait<0>();
    __syncthreads();

    for (int cc = 0; cc < CH / BK; ++cc) {
        int st = cc & 1;
        if (cc < CH / BK - 1) {
#pragma unroll
            for (int q = 0; q < 4; ++q) {
                unsigned long long d = (unsigned long long)__float_as_uint(hn[q]);
                shH[st ^ 1][hkk + 8 * q][hrow] = d | (d << 32);
            }
            int kb = (cc + 1) * BK;
#pragma unroll
            for (int i = 0; i < 16; ++i) {
                int idx = tid + i * 256;
                int kr = idx >> 7, c4 = (idx & 127) << 2;
                cpa16(smem_u32(&shW[st ^ 1][kr][c4]),
                      &Wm[(size_t)(kb + kr) * CH + c4]);
            }
            cp_commit();
            if (cc < CH / BK - 2) {
#pragma unroll
                for (int q = 0; q < 4; ++q)
                    hn[q] = hvalid ? hptr[(cc + 2) * BK + 8 * q] : 0.0f;
            }
        }
#pragma unroll
        for (int k = 0; k < BK; ++k) {
            const ulonglong2* wp = (const ulonglong2*)&shW[st][k][cg << 3];
            ulonglong2 w01 = wp[0];
            ulonglong2 w23 = wp[1];
            unsigned long long wv0 = w01.x, wv1 = w01.y, wv2 = w23.x, wv3 = w23.y;
            const ulonglong2* hp = (const ulonglong2*)&shH[st][k][rg << 3];
            ulonglong2 hA = hp[0], hB = hp[1], hC = hp[2], hD = hp[3];
            unsigned long long hv[8] = {hA.x, hA.y, hB.x, hB.y,
                                        hC.x, hC.y, hD.x, hD.y};
#pragma unroll
            for (int r = 0; r < 8; ++r) {
                FMA2(acc[r][0], hv[r], wv0);
                FMA2(acc[r][1], hv[r], wv1);
                FMA2(acc[r][2], hv[r], wv2);
                FMA2(acc[r][3], hv[r], wv3);
            }
        }
        if (cc < CH / BK - 1) cp_wait<0>();
        __syncthreads();
    }

    float bc[8];
#pragma unroll
    for (int j = 0; j < 8; ++j) bc[j] = Bv[(cg << 3) + j];
    float av[8][8];
#pragma unroll
    for (int r = 0; r < 8; ++r)
#pragma unroll
        for (int p = 0; p < 4; ++p) {
            unsigned long long v = acc[r][p];
            av[r][2 * p]     = __uint_as_float((unsigned)v) + bc[2 * p];
            av[r][2 * p + 1] = __uint_as_float((unsigned)(v >> 32)) + bc[2 * p + 1];
        }

    // row max + argmax (first-max semantics)
#pragma unroll
    for (int r = 0; r < 8; ++r) {
        float m = AV(r, 0);
        int ai = 0;
#pragma unroll
        for (int j = 1; j < 8; ++j) {
            float v = AV(r, j);
            if (v > m) { m = v; ai = j; }
        }
        int lr = (rg << 3) + r;
        red[lr][cg]  = m;
        redi[lr][cg] = (cg << 3) + ai;
    }
    __syncthreads();
    if (tid < BM) {
        float m = red[tid][0];
        int ai = redi[tid][0];
        for (int j = 1; j < 64; ++j) {
            float v = red[tid][j];
            if (v > m) { m = v; ai = redi[tid][j]; }
        }
        rowmax[tid] = m;
        rowarg[tid] = ai;
    }
    __syncthreads();

    // exp + row sum
#pragma unroll
    for (int r = 0; r < 8; ++r) {
        int lr = (rg << 3) + r;
        float m = rowmax[lr];
        float s = 0.0f;
#pragma unroll
        for (int j = 0; j < 8; ++j) {
            float e = __expf(AV(r, j) - m);
            AV(r, j) = e;
            s += e;
        }
        red[lr][cg] = s;
    }
    __syncthreads();
    if (tid < BM) {
        float s = 0.0f;
        for (int j = 0; j < 64; ++j) s += red[tid][j];
        rowinv[tid] = 1.0f / s;
    }
    __syncthreads();

#pragma unroll
    for (int r = 0; r < 8; ++r) {
        int lr = (rg << 3) + r;
        int gr = row0 + lr;
        if (gr < NN) {
            size_t base = (size_t)gr * CH + (cg << 3);
            if (base + 8 <= out_lim) {
                float inv = rowinv[lr];
                float4 o0 = make_float4(AV(r, 0) * inv, AV(r, 1) * inv,
                                        AV(r, 2) * inv, AV(r, 3) * inv);
                float4 o1 = make_float4(AV(r, 4) * inv, AV(r, 5) * inv,
                                        AV(r, 6) * inv, AV(r, 7) * inv);
                __stcs((float4*)&out[base], o0);
                __stcs((float4*)&out[base + 4], o1);
            }
        }
    }
    if (pred != nullptr && tid < BM && row0 + tid < NN) {
        size_t pidx = (size_t)(pred - outbase) + (row0 + tid);
        if (pidx < out_lim) pred[row0 + tid] = (float)rowarg[tid];
    }
}

// ---------------- launch -----------------------------------------------------
extern "C" void kernel_launch(void* const* d_in, const int* in_sizes, int n_in,
                              void* d_out, int out_size) {
    const float* x  = (const float*)d_in[0];
    const int*   e1 = (const int*)d_in[1];
    const int*   e2 = (const int*)d_in[2];
    const float* W1 = (const float*)d_in[3];
    const float* b1 = (const float*)d_in[4];
    const float* W2 = (const float*)d_in[5];
    const float* b2 = (const float*)d_in[6];

    float* out = (float*)d_out;
    float* logits1 = out;
    float* logits2 = out + (size_t)NN * CH;
    float* preds   = out + 2 * (size_t)NN * CH;
    size_t out_lim = (size_t)out_size;

    float *bufA, *bufB, *bufC;
    void* cntp;
    cudaGetSymbolAddress((void**)&bufA, g_bufA);
    cudaGetSymbolAddress((void**)&bufB, g_bufB);
    cudaGetSymbolAddress((void**)&bufC, g_bufC);
    cudaGetSymbolAddress(&cntp, g_cnt);

    // dynamic smem attribute (idempotent; not a stream op)
    cudaFuncSetAttribute(gemm_softmax_kernel,
                         cudaFuncAttributeMaxDynamicSharedMemorySize, DSMEM);

    // side stream + fork/join events (created once; deterministic thereafter)
    static cudaStream_t s2 = nullptr;
    static cudaEvent_t evB = nullptr, evG1 = nullptr;
    if (s2 == nullptr) {
        cudaStreamCreateWithFlags(&s2, cudaStreamNonBlocking);
        cudaEventCreateWithFlags(&evB, cudaEventDisableTiming);
        cudaEventCreateWithFlags(&evG1, cudaEventDisableTiming);
    }

    dim3 egrid((NE + 255) / 256, 2);
    int gblocks = (NN + BM - 1) / BM;

    cudaMemsetAsync(cntp, 0, 2 * NN * sizeof(int));        // memset node
    count2_kernel<<<egrid, 256>>>(e1, e2);                 // kernel 1
    scandis_kernel<<<2, 1024>>>();                         // kernel 2
    scatter2_kernel<<<egrid, 256>>>(e1, e2);               // kernel 3

    // conv-1 propagation on capture stream
    spmm_kernel<<<NN, 128>>>(0, (const float4*)x,    (float4*)bufA);  // 4 <- prof
    spmm_kernel<<<NN, 128>>>(0, (const float4*)bufA, (float4*)bufB);  // 5

    // fork: gemm1 (fma-bound) on side stream, co-resident with conv-2 spmm
    cudaEventRecord(evB, 0);
    cudaStreamWaitEvent(s2, evB, 0);
    gemm_softmax_kernel<<<gblocks, 256, DSMEM, s2>>>(bufB, W1, b1, logits1,
                                                     preds, out, out_lim);
    cudaEventRecord(evG1, s2);

    // conv-2 propagation + gemm on capture stream (LTS-bound overlaps gemm1)
    spmm_kernel<<<NN, 128>>>(1, (const float4*)x,    (float4*)bufA);
    spmm_kernel<<<NN, 128>>>(1, (const float4*)bufA, (float4*)bufC);
    gemm_softmax_kernel<<<gblocks, 256, DSMEM>>>(bufC, W2, b2, logits2,
                                                 nullptr, out, out_lim);

    // join: capture stream completes only after gemm1
    cudaStreamWaitEvent(0, evG1, 0);
}

// round 16
// speedup vs baseline: 1.0714x; 1.0714x over previous
#include <cuda_runtime.h>
#include <cstdint>
#include <cstddef>

#define NN  50000
#define NE  800000
#define CH  512
#define CH4 128   // CH/4 float4 per row
#define BM  32
#define BK  16

// ---------------- scratch (device globals) -----------------------------------
__device__ int   g_cnt[2][NN];
__device__ float g_dis[2][NN];
__device__ int   g_rowptr[2][NN + 1];
__device__ int   g_cursor[2][NN];
__device__ int   g_src[2][NE];
__device__ float g_wgt[2][NE];
__device__ __align__(16) float g_bufA[(size_t)NN * CH];
__device__ __align__(16) float g_bufB[(size_t)NN * CH];
__device__ __align__(16) float g_bufC[(size_t)NN * CH];

// ---------------- helpers -----------------------------------------------------
__device__ __forceinline__ uint32_t smem_u32(const void* p) {
    uint32_t a;
    asm("{ .reg .u64 t; cvta.to.shared.u64 t, %1; cvt.u32.u64 %0, t; }"
        : "=r"(a) : "l"(p));
    return a;
}
__device__ __forceinline__ void cpa16(uint32_t dst, const void* src) {
    asm volatile("cp.async.cg.shared.global [%0], [%1], 16;"
                 :: "r"(dst), "l"(src) : "memory");
}
__device__ __forceinline__ void cp_commit() {
    asm volatile("cp.async.commit_group;" ::: "memory");
}
template <int N>
__device__ __forceinline__ void cp_wait() {
    asm volatile("cp.async.wait_group %0;" :: "n"(N) : "memory");
}

// ---------------- graph preprocessing (per-graph, pipelined on 2 streams) ----
__global__ void count_kernel(const int* __restrict__ ei, int g) {
    int e = blockIdx.x * blockDim.x + threadIdx.x;
    if (e < NE) {
        int c = ei[NE + e];
        if ((unsigned)c < (unsigned)NN) atomicAdd(&g_cnt[g][c], 1);
    }
}

// single block: dis + exclusive scan of counts (warp-shuffle scan)
__global__ void scandis_kernel(int g) {
    __shared__ int sw[32];
    __shared__ int s_carry;
    int t = threadIdx.x, l = t & 31, w = t >> 5;
    const unsigned full = 0xffffffffu;
    if (t == 0) s_carry = 0;
    __syncthreads();
    for (int base = 0; base < NN; base += 1024) {
        int i = base + t;
        int v = (i < NN) ? g_cnt[g][i] : 0;
        if (i < NN) g_dis[g][i] = rsqrtf((float)v + 1.0f);  // +1 self loop
        int incl = v;
#pragma unroll
        for (int o = 1; o < 32; o <<= 1) {
            int u = __shfl_up_sync(full, incl, o);
            if (l >= o) incl += u;
        }
        if (l == 31) sw[w] = incl;
        __syncthreads();
        if (w == 0) {
            int s = sw[l];
#pragma unroll
            for (int o = 1; o < 32; o <<= 1) {
                int u = __shfl_up_sync(full, s, o);
                if (l >= o) s += u;
            }
            sw[l] = s;
        }
        __syncthreads();
        int woff = w ? sw[w - 1] : 0;
        int excl = s_carry + woff + incl - v;
        if (i < NN) {
            g_rowptr[g][i] = excl;
            g_cursor[g][i] = excl;
        }
        __syncthreads();
        if (t == 1023) s_carry += sw[31];
        __syncthreads();
    }
    if (t == 0) g_rowptr[g][NN] = s_carry;
}

__global__ void scatter_kernel(const int* __restrict__ ei, int g) {
    int e = blockIdx.x * blockDim.x + threadIdx.x;
    if (e < NE) {
        int r = ei[e];
        int c = ei[NE + e];
        if ((unsigned)r < (unsigned)NN && (unsigned)c < (unsigned)NN) {
            int pos = atomicAdd(&g_cursor[g][c], 1);
            g_src[g][pos] = r;
            g_wgt[g][pos] = g_dis[g][r] * g_dis[g][c];
        }
    }
}

// ---------------- SpMM: gather-CSR, unroll x8 (R12-proven) -------------------
__global__ __launch_bounds__(128) void spmm_kernel(
    int g, const float4* __restrict__ in, float4* __restrict__ out) {
    int i = blockIdx.x, t = threadIdx.x;  // thread owns 4 channels of row i
    const int*   __restrict__ src = g_src[g];
    const float* __restrict__ wgt = g_wgt[g];
    float di = g_dis[g][i];
    int beg = g_rowptr[g][i], end = g_rowptr[g][i + 1];
    float4 h = in[(size_t)i * CH4 + t];
    float ws = di * di;  // self loop weight
    float4 a0 = make_float4(h.x * ws, h.y * ws, h.z * ws, h.w * ws);
    float4 a1 = make_float4(0, 0, 0, 0);
    float4 a2 = make_float4(0, 0, 0, 0);
    float4 a3 = make_float4(0, 0, 0, 0);
    int j = beg;
    int jal = (beg + 3) & ~3;   // align to 4-edge boundary for 16B vector loads
    if (jal > end) jal = end;
    for (; j < jal; ++j) {
        int s = __ldcs(&src[j]);
        float w = __ldcs(&wgt[j]);
        float4 v = in[(size_t)s * CH4 + t];
        a0.x = fmaf(w, v.x, a0.x); a0.y = fmaf(w, v.y, a0.y);
        a0.z = fmaf(w, v.z, a0.z); a0.w = fmaf(w, v.w, a0.w);
    }
    for (; j + 8 <= end; j += 8) {
        int4 sA = __ldcs((const int4*)&src[j]);
        int4 sB = __ldcs((const int4*)&src[j + 4]);
        float4 wA = __ldcs((const float4*)&wgt[j]);
        float4 wB = __ldcs((const float4*)&wgt[j + 4]);
        float4 v0 = in[(size_t)sA.x * CH4 + t];
        float4 v1 = in[(size_t)sA.y * CH4 + t];
        float4 v2 = in[(size_t)sA.z * CH4 + t];
        float4 v3 = in[(size_t)sA.w * CH4 + t];
        float4 v4 = in[(size_t)sB.x * CH4 + t];
        float4 v5 = in[(size_t)sB.y * CH4 + t];
        float4 v6 = in[(size_t)sB.z * CH4 + t];
        float4 v7 = in[(size_t)sB.w * CH4 + t];
        a0.x = fmaf(wA.x, v0.x, a0.x); a0.y = fmaf(wA.x, v0.y, a0.y);
        a0.z = fmaf(wA.x, v0.z, a0.z); a0.w = fmaf(wA.x, v0.w, a0.w);
        a1.x = fmaf(wA.y, v1.x, a1.x); a1.y = fmaf(wA.y, v1.y, a1.y);
        a1.z = fmaf(wA.y, v1.z, a1.z); a1.w = fmaf(wA.y, v1.w, a1.w);
        a2.x = fmaf(wA.z, v2.x, a2.x); a2.y = fmaf(wA.z, v2.y, a2.y);
        a2.z = fmaf(wA.z, v2.z, a2.z); a2.w = fmaf(wA.z, v2.w, a2.w);
        a3.x = fmaf(wA.w, v3.x, a3.x); a3.y = fmaf(wA.w, v3.y, a3.y);
        a3.z = fmaf(wA.w, v3.z, a3.z); a3.w = fmaf(wA.w, v3.w, a3.w);
        a0.x = fmaf(wB.x, v4.x, a0.x); a0.y = fmaf(wB.x, v4.y, a0.y);
        a0.z = fmaf(wB.x, v4.z, a0.z); a0.w = fmaf(wB.x, v4.w, a0.w);
        a1.x = fmaf(wB.y, v5.x, a1.x); a1.y = fmaf(wB.y, v5.y, a1.y);
        a1.z = fmaf(wB.y, v5.z, a1.z); a1.w = fmaf(wB.y, v5.w, a1.w);
        a2.x = fmaf(wB.z, v6.x, a2.x); a2.y = fmaf(wB.z, v6.y, a2.y);
        a2.z = fmaf(wB.z, v6.z, a2.z); a2.w = fmaf(wB.z, v6.w, a2.w);
        a3.x = fmaf(wB.w, v7.x, a3.x); a3.y = fmaf(wB.w, v7.y, a3.y);
        a3.z = fmaf(wB.w, v7.z, a3.z); a3.w = fmaf(wB.w, v7.w, a3.w);
    }
    for (; j < end; ++j) {
        int s = __ldcs(&src[j]);
        float w = __ldcs(&wgt[j]);
        float4 v = in[(size_t)s * CH4 + t];
        a0.x = fmaf(w, v.x, a0.x); a0.y = fmaf(w, v.y, a0.y);
        a0.z = fmaf(w, v.z, a0.z); a0.w = fmaf(w, v.w, a0.w);
    }
    float4 acc = make_float4((a0.x + a1.x) + (a2.x + a3.x),
                             (a0.y + a1.y) + (a2.y + a3.y),
                             (a0.z + a1.z) + (a2.z + a3.z),
                             (a0.w + a1.w) + (a2.w + a3.w));
    out[(size_t)i * CH4 + t] = acc;
}

// ---------------- fused GEMM (f32x2, double-buffered, BK=16) -----------------
// R14-proven optimum: 256 threads, BM=32, 74.2KB dynamic smem, 2 CTAs/SM.
#define FMA2(d, a, b) \
    asm("fma.rn.f32x2 %0, %1, %2, %0;" : "+l"(d) : "l"(a), "l"(b))
#define AV(r, j) av[(r)][(j)]

#define SHW_BYTES (2 * BK * CH * 4)          // 65536
#define SHH_BYTES (2 * BK * (BM + 2) * 8)    // 8704
#define DSMEM (SHW_BYTES + SHH_BYTES)        // 74240

__global__ __launch_bounds__(256) void gemm_softmax_kernel(
    const float* __restrict__ Hm, const float* __restrict__ Wm,
    const float* __restrict__ Bv, float* __restrict__ out,
    float* __restrict__ pred, float* __restrict__ outbase, size_t out_lim) {
    extern __shared__ __align__(16) unsigned char smem[];
    __shared__ float rowmax[BM];
    __shared__ float rowinv[BM];
    __shared__ int   rowarg[BM];

    float (*shW)[BK][CH] = (float(*)[BK][CH])smem;                  // [2][16][512]
    unsigned long long (*shH)[BK][BM + 2] =
        (unsigned long long(*)[BK][BM + 2])(smem + SHW_BYTES);      // [2][16][34]
    float (*red)[65]  = (float(*)[65])smem;                         // overlay
    int   (*redi)[65] = (int(*)[65])(smem + 16640);

    int tid = threadIdx.x;
    int cg = tid & 63;          // 8-column group
    int rg = tid >> 6;          // 0..3: 8-row group
    int row0 = blockIdx.x * BM;

    unsigned long long acc[8][4];
#pragma unroll
    for (int r = 0; r < 8; ++r)
#pragma unroll
        for (int p = 0; p < 4; ++p) acc[r][p] = 0ULL;

    int hrow = tid >> 3;        // 0..31
    int hkk  = tid & 7;         // thread writes k = hkk and k = hkk+8
    int hgr  = row0 + hrow;
    bool hvalid = (hgr < NN);
    const float* hptr = &Hm[(size_t)(hvalid ? hgr : 0) * CH + hkk];

    // W-tile cp.async: 8 x 16B per thread covers 16x512 floats
#pragma unroll
    for (int i = 0; i < 8; ++i) {
        int idx = tid + i * 256;
        int kr = idx >> 7, c4 = (idx & 127) << 2;
        cpa16(smem_u32(&shW[0][kr][c4]), &Wm[(size_t)kr * CH + c4]);
    }
    cp_commit();
    {
        float v0 = hvalid ? hptr[0] : 0.0f;
        float v1 = hvalid ? hptr[8] : 0.0f;
        unsigned long long d0 = (unsigned long long)__float_as_uint(v0);
        unsigned long long d1 = (unsigned long long)__float_as_uint(v1);
        shH[0][hkk][hrow]     = d0 | (d0 << 32);
        shH[0][hkk + 8][hrow] = d1 | (d1 << 32);
    }
    float hn0 = hvalid ? hptr[BK] : 0.0f;
    float hn1 = hvalid ? hptr[BK + 8] : 0.0f;
    cp_wait<0>();
    __syncthreads();

    for (int cc = 0; cc < CH / BK; ++cc) {
        int st = cc & 1;
        if (cc < CH / BK - 1) {
            unsigned long long d0 = (unsigned long long)__float_as_uint(hn0);
            unsigned long long d1 = (unsigned long long)__float_as_uint(hn1);
            shH[st ^ 1][hkk][hrow]     = d0 | (d0 << 32);
            shH[st ^ 1][hkk + 8][hrow] = d1 | (d1 << 32);
            int kb = (cc + 1) * BK;
#pragma unroll
            for (int i = 0; i < 8; ++i) {
                int idx = tid + i * 256;
                int kr = idx >> 7, c4 = (idx & 127) << 2;
                cpa16(smem_u32(&shW[st ^ 1][kr][c4]),
                      &Wm[(size_t)(kb + kr) * CH + c4]);
            }
            cp_commit();
            if (cc < CH / BK - 2) {
                hn0 = hvalid ? hptr[(cc + 2) * BK] : 0.0f;
                hn1 = hvalid ? hptr[(cc + 2) * BK + 8] : 0.0f;
            }
        }
#pragma unroll
        for (int k = 0; k < BK; ++k) {
            const ulonglong2* wp = (const ulonglong2*)&shW[st][k][cg << 3];
            ulonglong2 w01 = wp[0];
            ulonglong2 w23 = wp[1];
            unsigned long long wv0 = w01.x, wv1 = w01.y, wv2 = w23.x, wv3 = w23.y;
            const ulonglong2* hp = (const ulonglong2*)&shH[st][k][rg << 3];
            ulonglong2 hA = hp[0], hB = hp[1], hC = hp[2], hD = hp[3];
            unsigned long long hv[8] = {hA.x, hA.y, hB.x, hB.y,
                                        hC.x, hC.y, hD.x, hD.y};
#pragma unroll
            for (int r = 0; r < 8; ++r) {
                FMA2(acc[r][0], hv[r], wv0);
                FMA2(acc[r][1], hv[r], wv1);
                FMA2(acc[r][2], hv[r], wv2);
                FMA2(acc[r][3], hv[r], wv3);
            }
        }
        if (cc < CH / BK - 1) cp_wait<0>();
        __syncthreads();
    }

    float bc[8];
#pragma unroll
    for (int j = 0; j < 8; ++j) bc[j] = Bv[(cg << 3) + j];
    float av[8][8];
#pragma unroll
    for (int r = 0; r < 8; ++r)
#pragma unroll
        for (int p = 0; p < 4; ++p) {
            unsigned long long v = acc[r][p];
            av[r][2 * p]     = __uint_as_float((unsigned)v) + bc[2 * p];
            av[r][2 * p + 1] = __uint_as_float((unsigned)(v >> 32)) + bc[2 * p + 1];
        }

    // row max + argmax (first-max semantics)
#pragma unroll
    for (int r = 0; r < 8; ++r) {
        float m = AV(r, 0);
        int ai = 0;
#pragma unroll
        for (int j = 1; j < 8; ++j) {
            float v = AV(r, j);
            if (v > m) { m = v; ai = j; }
        }
        int lr = (rg << 3) + r;
        red[lr][cg]  = m;
        redi[lr][cg] = (cg << 3) + ai;
    }
    __syncthreads();
    if (tid < BM) {
        float m = red[tid][0];
        int ai = redi[tid][0];
        for (int j = 1; j < 64; ++j) {
            float v = red[tid][j];
            if (v > m) { m = v; ai = redi[tid][j]; }
        }
        rowmax[tid] = m;
        rowarg[tid] = ai;
    }
    __syncthreads();

    // exp + row sum
#pragma unroll
    for (int r = 0; r < 8; ++r) {
        int lr = (rg << 3) + r;
        float m = rowmax[lr];
        float s = 0.0f;
#pragma unroll
        for (int j = 0; j < 8; ++j) {
            float e = __expf(AV(r, j) - m);
            AV(r, j) = e;
            s += e;
        }
        red[lr][cg] = s;
    }
    __syncthreads();
    if (tid < BM) {
        float s = 0.0f;
        for (int j = 0; j < 64; ++j) s += red[tid][j];
        rowinv[tid] = 1.0f / s;
    }
    __syncthreads();

#pragma unroll
    for (int r = 0; r < 8; ++r) {
        int lr = (rg << 3) + r;
        int gr = row0 + lr;
        if (gr < NN) {
            size_t base = (size_t)gr * CH + (cg << 3);
            if (base + 8 <= out_lim) {
                float inv = rowinv[lr];
                float4 o0 = make_float4(AV(r, 0) * inv, AV(r, 1) * inv,
                                        AV(r, 2) * inv, AV(r, 3) * inv);
                float4 o1 = make_float4(AV(r, 4) * inv, AV(r, 5) * inv,
                                        AV(r, 6) * inv, AV(r, 7) * inv);
                __stcs((float4*)&out[base], o0);
                __stcs((float4*)&out[base + 4], o1);
            }
        }
    }
    if (pred != nullptr && tid < BM && row0 + tid < NN) {
        size_t pidx = (size_t)(pred - outbase) + (row0 + tid);
        if (pidx < out_lim) pred[row0 + tid] = (float)rowarg[tid];
    }
}

// ---------------- launch -----------------------------------------------------
extern "C" void kernel_launch(void* const* d_in, const int* in_sizes, int n_in,
                              void* d_out, int out_size) {
    const float* x  = (const float*)d_in[0];
    const int*   e1 = (const int*)d_in[1];
    const int*   e2 = (const int*)d_in[2];
    const float* W1 = (const float*)d_in[3];
    const float* b1 = (const float*)d_in[4];
    const float* W2 = (const float*)d_in[5];
    const float* b2 = (const float*)d_in[6];

    float* out = (float*)d_out;
    float* logits1 = out;
    float* logits2 = out + (size_t)NN * CH;
    float* preds   = out + 2 * (size_t)NN * CH;
    size_t out_lim = (size_t)out_size;

    float *bufA, *bufB, *bufC;
    void* cntp;
    cudaGetSymbolAddress((void**)&bufA, g_bufA);
    cudaGetSymbolAddress((void**)&bufB, g_bufB);
    cudaGetSymbolAddress((void**)&bufC, g_bufC);
    cudaGetSymbolAddress(&cntp, g_cnt);

    // dynamic smem attribute (idempotent; not a stream op)
    cudaFuncSetAttribute(gemm_softmax_kernel,
                         cudaFuncAttributeMaxDynamicSharedMemorySize, DSMEM);

    // side stream + fork/join events (created once; deterministic thereafter)
    static cudaStream_t s2 = nullptr;
    static cudaEvent_t evM = nullptr, evP1 = nullptr, evB = nullptr,
                       evG1 = nullptr;
    if (s2 == nullptr) {
        cudaStreamCreateWithFlags(&s2, cudaStreamNonBlocking);
        cudaEventCreateWithFlags(&evM, cudaEventDisableTiming);
        cudaEventCreateWithFlags(&evP1, cudaEventDisableTiming);
        cudaEventCreateWithFlags(&evB, cudaEventDisableTiming);
        cudaEventCreateWithFlags(&evG1, cudaEventDisableTiming);
    }

    int eblocks = (NE + 255) / 256;
    int gblocks = (NN + BM - 1) / BM;

    cudaMemsetAsync(cntp, 0, 2 * NN * sizeof(int));        // memset node
    cudaEventRecord(evM, 0);

    // graph-1 preprocessing on side stream (overlaps graph-0 pre + spmm)
    cudaStreamWaitEvent(s2, evM, 0);
    count_kernel<<<eblocks, 256, 0, s2>>>(e2, 1);
    scandis_kernel<<<1, 1024, 0, s2>>>(1);
    scatter_kernel<<<eblocks, 256, 0, s2>>>(e2, 1);
    cudaEventRecord(evP1, s2);

    // graph-0 preprocessing + propagation on capture stream
    count_kernel<<<eblocks, 256>>>(e1, 0);
    scandis_kernel<<<1, 1024>>>(0);
    scatter_kernel<<<eblocks, 256>>>(e1, 0);
    spmm_kernel<<<NN, 128>>>(0, (const float4*)x,    (float4*)bufA);
    spmm_kernel<<<NN, 128>>>(0, (const float4*)bufA, (float4*)bufB);
    cudaEventRecord(evB, 0);

    // gemm1 on side stream (after its graph-1 pre chain; co-resident w/ spmm)
    cudaStreamWaitEvent(s2, evB, 0);
    gemm_softmax_kernel<<<gblocks, 256, DSMEM, s2>>>(bufB, W1, b1, logits1,
                                                     preds, out, out_lim);
    cudaEventRecord(evG1, s2);

    // conv-2 propagation + gemm on capture stream (needs graph-1 pre done)
    cudaStreamWaitEvent(0, evP1, 0);
    spmm_kernel<<<NN, 128>>>(1, (const float4*)x,    (float4*)bufA);
    spmm_kernel<<<NN, 128>>>(1, (const float4*)bufA, (float4*)bufC);
    gemm_softmax_kernel<<<gblocks, 256, DSMEM>>>(bufC, W2, b2, logits2,
                                                 nullptr, out, out_lim);

    // join: capture stream completes only after gemm1
    cudaStreamWaitEvent(0, evG1, 0);
}

// round 17
// speedup vs baseline: 1.1577x; 1.0806x over previous
#include <cuda_runtime.h>
#include <cstdint>
#include <cstddef>

#define NN  50000
#define NE  800000
#define CH  512
#define CH4 128   // CH/4 float4 per row
#define BM  32
#define BK  16

// ---------------- scratch (device globals) -----------------------------------
__device__ int   g_cnt[2][NN];
__device__ float g_dis[2][NN];
__device__ int   g_rowptr[2][NN + 1];
__device__ int   g_cursor[2][NN];
__device__ int   g_src[2][NE];
__device__ float g_wgt[2][NE];
__device__ __align__(16) float g_bufA[(size_t)NN * CH];
__device__ __align__(16) float g_bufB[(size_t)NN * CH];
__device__ __align__(16) float g_bufC[(size_t)NN * CH];

// ---------------- helpers -----------------------------------------------------
__device__ __forceinline__ uint32_t smem_u32(const void* p) {
    uint32_t a;
    asm("{ .reg .u64 t; cvta.to.shared.u64 t, %1; cvt.u32.u64 %0, t; }"
        : "=r"(a) : "l"(p));
    return a;
}
__device__ __forceinline__ void cpa16(uint32_t dst, const void* src) {
    asm volatile("cp.async.cg.shared.global [%0], [%1], 16;"
                 :: "r"(dst), "l"(src) : "memory");
}
__device__ __forceinline__ void cp_commit() {
    asm volatile("cp.async.commit_group;" ::: "memory");
}
template <int N>
__device__ __forceinline__ void cp_wait() {
    asm volatile("cp.async.wait_group %0;" :: "n"(N) : "memory");
}

// ---------------- graph preprocessing (per-graph, pipelined on 2 streams) ----
__global__ void count_kernel(const int* __restrict__ ei, int g) {
    int e = blockIdx.x * blockDim.x + threadIdx.x;
    if (e < NE) {
        int c = ei[NE + e];
        if ((unsigned)c < (unsigned)NN) atomicAdd(&g_cnt[g][c], 1);
    }
}

// single block: dis + exclusive scan of counts (warp-shuffle scan)
__global__ void scandis_kernel(int g) {
    __shared__ int sw[32];
    __shared__ int s_carry;
    int t = threadIdx.x, l = t & 31, w = t >> 5;
    const unsigned full = 0xffffffffu;
    if (t == 0) s_carry = 0;
    __syncthreads();
    for (int base = 0; base < NN; base += 1024) {
        int i = base + t;
        int v = (i < NN) ? g_cnt[g][i] : 0;
        if (i < NN) g_dis[g][i] = rsqrtf((float)v + 1.0f);  // +1 self loop
        int incl = v;
#pragma unroll
        for (int o = 1; o < 32; o <<= 1) {
            int u = __shfl_up_sync(full, incl, o);
            if (l >= o) incl += u;
        }
        if (l == 31) sw[w] = incl;
        __syncthreads();
        if (w == 0) {
            int s = sw[l];
#pragma unroll
            for (int o = 1; o < 32; o <<= 1) {
                int u = __shfl_up_sync(full, s, o);
                if (l >= o) s += u;
            }
            sw[l] = s;
        }
        __syncthreads();
        int woff = w ? sw[w - 1] : 0;
        int excl = s_carry + woff + incl - v;
        if (i < NN) {
            g_rowptr[g][i] = excl;
            g_cursor[g][i] = excl;
        }
        __syncthreads();
        if (t == 1023) s_carry += sw[31];
        __syncthreads();
    }
    if (t == 0) g_rowptr[g][NN] = s_carry;
}

__global__ void scatter_kernel(const int* __restrict__ ei, int g) {
    int e = blockIdx.x * blockDim.x + threadIdx.x;
    if (e < NE) {
        int r = ei[e];
        int c = ei[NE + e];
        if ((unsigned)r < (unsigned)NN && (unsigned)c < (unsigned)NN) {
            int pos = atomicAdd(&g_cursor[g][c], 1);
            g_src[g][pos] = r;
            g_wgt[g][pos] = g_dis[g][r] * g_dis[g][c];
        }
    }
}

// ---------------- SpMM: gather-CSR, unroll x8, CHANNEL-SPLIT halves ----------
// coff = float4 column offset (0 or 64). Per half-pass resident set is
// 51MB in + 51MB out < L2, so gathers stay L2-resident (kills 44% DRAM).
__global__ __launch_bounds__(64) void spmm_kernel(
    int g, const float4* __restrict__ in, float4* __restrict__ out, int coff) {
    int i = blockIdx.x;
    int t = coff + threadIdx.x;  // float4 column within the row
    const int*   __restrict__ src = g_src[g];
    const float* __restrict__ wgt = g_wgt[g];
    float di = g_dis[g][i];
    int beg = g_rowptr[g][i], end = g_rowptr[g][i + 1];
    float4 h = in[(size_t)i * CH4 + t];
    float ws = di * di;  // self loop weight
    float4 a0 = make_float4(h.x * ws, h.y * ws, h.z * ws, h.w * ws);
    float4 a1 = make_float4(0, 0, 0, 0);
    float4 a2 = make_float4(0, 0, 0, 0);
    float4 a3 = make_float4(0, 0, 0, 0);
    int j = beg;
    int jal = (beg + 3) & ~3;   // align to 4-edge boundary for 16B vector loads
    if (jal > end) jal = end;
    for (; j < jal; ++j) {
        int s = __ldcs(&src[j]);
        float w = __ldcs(&wgt[j]);
        float4 v = in[(size_t)s * CH4 + t];
        a0.x = fmaf(w, v.x, a0.x); a0.y = fmaf(w, v.y, a0.y);
        a0.z = fmaf(w, v.z, a0.z); a0.w = fmaf(w, v.w, a0.w);
    }
    for (; j + 8 <= end; j += 8) {
        int4 sA = __ldcs((const int4*)&src[j]);
        int4 sB = __ldcs((const int4*)&src[j + 4]);
        float4 wA = __ldcs((const float4*)&wgt[j]);
        float4 wB = __ldcs((const float4*)&wgt[j + 4]);
        float4 v0 = in[(size_t)sA.x * CH4 + t];
        float4 v1 = in[(size_t)sA.y * CH4 + t];
        float4 v2 = in[(size_t)sA.z * CH4 + t];
        float4 v3 = in[(size_t)sA.w * CH4 + t];
        float4 v4 = in[(size_t)sB.x * CH4 + t];
        float4 v5 = in[(size_t)sB.y * CH4 + t];
        float4 v6 = in[(size_t)sB.z * CH4 + t];
        float4 v7 = in[(size_t)sB.w * CH4 + t];
        a0.x = fmaf(wA.x, v0.x, a0.x); a0.y = fmaf(wA.x, v0.y, a0.y);
        a0.z = fmaf(wA.x, v0.z, a0.z); a0.w = fmaf(wA.x, v0.w, a0.w);
        a1.x = fmaf(wA.y, v1.x, a1.x); a1.y = fmaf(wA.y, v1.y, a1.y);
        a1.z = fmaf(wA.y, v1.z, a1.z); a1.w = fmaf(wA.y, v1.w, a1.w);
        a2.x = fmaf(wA.z, v2.x, a2.x); a2.y = fmaf(wA.z, v2.y, a2.y);
        a2.z = fmaf(wA.z, v2.z, a2.z); a2.w = fmaf(wA.z, v2.w, a2.w);
        a3.x = fmaf(wA.w, v3.x, a3.x); a3.y = fmaf(wA.w, v3.y, a3.y);
        a3.z = fmaf(wA.w, v3.z, a3.z); a3.w = fmaf(wA.w, v3.w, a3.w);
        a0.x = fmaf(wB.x, v4.x, a0.x); a0.y = fmaf(wB.x, v4.y, a0.y);
        a0.z = fmaf(wB.x, v4.z, a0.z); a0.w = fmaf(wB.x, v4.w, a0.w);
        a1.x = fmaf(wB.y, v5.x, a1.x); a1.y = fmaf(wB.y, v5.y, a1.y);
        a1.z = fmaf(wB.y, v5.z, a1.z); a1.w = fmaf(wB.y, v5.w, a1.w);
        a2.x = fmaf(wB.z, v6.x, a2.x); a2.y = fmaf(wB.z, v6.y, a2.y);
        a2.z = fmaf(wB.z, v6.z, a2.z); a2.w = fmaf(wB.z, v6.w, a2.w);
        a3.x = fmaf(wB.w, v7.x, a3.x); a3.y = fmaf(wB.w, v7.y, a3.y);
        a3.z = fmaf(wB.w, v7.z, a3.z); a3.w = fmaf(wB.w, v7.w, a3.w);
    }
    for (; j < end; ++j) {
        int s = __ldcs(&src[j]);
        float w = __ldcs(&wgt[j]);
        float4 v = in[(size_t)s * CH4 + t];
        a0.x = fmaf(w, v.x, a0.x); a0.y = fmaf(w, v.y, a0.y);
        a0.z = fmaf(w, v.z, a0.z); a0.w = fmaf(w, v.w, a0.w);
    }
    float4 acc = make_float4((a0.x + a1.x) + (a2.x + a3.x),
                             (a0.y + a1.y) + (a2.y + a3.y),
                             (a0.z + a1.z) + (a2.z + a3.z),
                             (a0.w + a1.w) + (a2.w + a3.w));
    out[(size_t)i * CH4 + t] = acc;
}

// ---------------- fused GEMM (f32x2, double-buffered, BK=16) -----------------
// R14-proven optimum: 256 threads, BM=32, 74.2KB dynamic smem, 2 CTAs/SM.
#define FMA2(d, a, b) \
    asm("fma.rn.f32x2 %0, %1, %2, %0;" : "+l"(d) : "l"(a), "l"(b))
#define AV(r, j) av[(r)][(j)]

#define SHW_BYTES (2 * BK * CH * 4)          // 65536
#define SHH_BYTES (2 * BK * (BM + 2) * 8)    // 8704
#define DSMEM (SHW_BYTES + SHH_BYTES)        // 74240

__global__ __launch_bounds__(256) void gemm_softmax_kernel(
    const float* __restrict__ Hm, const float* __restrict__ Wm,
    const float* __restrict__ Bv, float* __restrict__ out,
    float* __restrict__ pred, float* __restrict__ outbase, size_t out_lim) {
    extern __shared__ __align__(16) unsigned char smem[];
    __shared__ float rowmax[BM];
    __shared__ float rowinv[BM];
    __shared__ int   rowarg[BM];

    float (*shW)[BK][CH] = (float(*)[BK][CH])smem;                  // [2][16][512]
    unsigned long long (*shH)[BK][BM + 2] =
        (unsigned long long(*)[BK][BM + 2])(smem + SHW_BYTES);      // [2][16][34]
    float (*red)[65]  = (float(*)[65])smem;                         // overlay
    int   (*redi)[65] = (int(*)[65])(smem + 16640);

    int tid = threadIdx.x;
    int cg = tid & 63;          // 8-column group
    int rg = tid >> 6;          // 0..3: 8-row group
    int row0 = blockIdx.x * BM;

    unsigned long long acc[8][4];
#pragma unroll
    for (int r = 0; r < 8; ++r)
#pragma unroll
        for (int p = 0; p < 4; ++p) acc[r][p] = 0ULL;

    int hrow = tid >> 3;        // 0..31
    int hkk  = tid & 7;         // thread writes k = hkk and k = hkk+8
    int hgr  = row0 + hrow;
    bool hvalid = (hgr < NN);
    const float* hptr = &Hm[(size_t)(hvalid ? hgr : 0) * CH + hkk];

    // W-tile cp.async: 8 x 16B per thread covers 16x512 floats
#pragma unroll
    for (int i = 0; i < 8; ++i) {
        int idx = tid + i * 256;
        int kr = idx >> 7, c4 = (idx & 127) << 2;
        cpa16(smem_u32(&shW[0][kr][c4]), &Wm[(size_t)kr * CH + c4]);
    }
    cp_commit();
    {
        float v0 = hvalid ? hptr[0] : 0.0f;
        float v1 = hvalid ? hptr[8] : 0.0f;
        unsigned long long d0 = (unsigned long long)__float_as_uint(v0);
        unsigned long long d1 = (unsigned long long)__float_as_uint(v1);
        shH[0][hkk][hrow]     = d0 | (d0 << 32);
        shH[0][hkk + 8][hrow] = d1 | (d1 << 32);
    }
    float hn0 = hvalid ? hptr[BK] : 0.0f;
    float hn1 = hvalid ? hptr[BK + 8] : 0.0f;
    cp_wait<0>();
    __syncthreads();

    for (int cc = 0; cc < CH / BK; ++cc) {
        int st = cc & 1;
        if (cc < CH / BK - 1) {
            unsigned long long d0 = (unsigned long long)__float_as_uint(hn0);
            unsigned long long d1 = (unsigned long long)__float_as_uint(hn1);
            shH[st ^ 1][hkk][hrow]     = d0 | (d0 << 32);
            shH[st ^ 1][hkk + 8][hrow] = d1 | (d1 << 32);
            int kb = (cc + 1) * BK;
#pragma unroll
            for (int i = 0; i < 8; ++i) {
                int idx = tid + i * 256;
                int kr = idx >> 7, c4 = (idx & 127) << 2;
                cpa16(smem_u32(&shW[st ^ 1][kr][c4]),
                      &Wm[(size_t)(kb + kr) * CH + c4]);
            }
            cp_commit();
            if (cc < CH / BK - 2) {
                hn0 = hvalid ? hptr[(cc + 2) * BK] : 0.0f;
                hn1 = hvalid ? hptr[(cc + 2) * BK + 8] : 0.0f;
            }
        }
#pragma unroll
        for (int k = 0; k < BK; ++k) {
            const ulonglong2* wp = (const ulonglong2*)&shW[st][k][cg << 3];
            ulonglong2 w01 = wp[0];
            ulonglong2 w23 = wp[1];
            unsigned long long wv0 = w01.x, wv1 = w01.y, wv2 = w23.x, wv3 = w23.y;
            const ulonglong2* hp = (const ulonglong2*)&shH[st][k][rg << 3];
            ulonglong2 hA = hp[0], hB = hp[1], hC = hp[2], hD = hp[3];
            unsigned long long hv[8] = {hA.x, hA.y, hB.x, hB.y,
                                        hC.x, hC.y, hD.x, hD.y};
#pragma unroll
            for (int r = 0; r < 8; ++r) {
                FMA2(acc[r][0], hv[r], wv0);
                FMA2(acc[r][1], hv[r], wv1);
                FMA2(acc[r][2], hv[r], wv2);
                FMA2(acc[r][3], hv[r], wv3);
            }
        }
        if (cc < CH / BK - 1) cp_wait<0>();
        __syncthreads();
    }

    float bc[8];
#pragma unroll
    for (int j = 0; j < 8; ++j) bc[j] = Bv[(cg << 3) + j];
    float av[8][8];
#pragma unroll
    for (int r = 0; r < 8; ++r)
#pragma unroll
        for (int p = 0; p < 4; ++p) {
            unsigned long long v = acc[r][p];
            av[r][2 * p]     = __uint_as_float((unsigned)v) + bc[2 * p];
            av[r][2 * p + 1] = __uint_as_float((unsigned)(v >> 32)) + bc[2 * p + 1];
        }

    // row max + argmax (first-max semantics)
#pragma unroll
    for (int r = 0; r < 8; ++r) {
        float m = AV(r, 0);
        int ai = 0;
#pragma unroll
        for (int j = 1; j < 8; ++j) {
            float v = AV(r, j);
            if (v > m) { m = v; ai = j; }
        }
        int lr = (rg << 3) + r;
        red[lr][cg]  = m;
        redi[lr][cg] = (cg << 3) + ai;
    }
    __syncthreads();
    if (tid < BM) {
        float m = red[tid][0];
        int ai = redi[tid][0];
        for (int j = 1; j < 64; ++j) {
            float v = red[tid][j];
            if (v > m) { m = v; ai = redi[tid][j]; }
        }
        rowmax[tid] = m;
        rowarg[tid] = ai;
    }
    __syncthreads();

    // exp + row sum
#pragma unroll
    for (int r = 0; r < 8; ++r) {
        int lr = (rg << 3) + r;
        float m = rowmax[lr];
        float s = 0.0f;
#pragma unroll
        for (int j = 0; j < 8; ++j) {
            float e = __expf(AV(r, j) - m);
            AV(r, j) = e;
            s += e;
        }
        red[lr][cg] = s;
    }
    __syncthreads();
    if (tid < BM) {
        float s = 0.0f;
        for (int j = 0; j < 64; ++j) s += red[tid][j];
        rowinv[tid] = 1.0f / s;
    }
    __syncthreads();

#pragma unroll
    for (int r = 0; r < 8; ++r) {
        int lr = (rg << 3) + r;
        int gr = row0 + lr;
        if (gr < NN) {
            size_t base = (size_t)gr * CH + (cg << 3);
            if (base + 8 <= out_lim) {
                float inv = rowinv[lr];
                float4 o0 = make_float4(AV(r, 0) * inv, AV(r, 1) * inv,
                                        AV(r, 2) * inv, AV(r, 3) * inv);
                float4 o1 = make_float4(AV(r, 4) * inv, AV(r, 5) * inv,
                                        AV(r, 6) * inv, AV(r, 7) * inv);
                __stcs((float4*)&out[base], o0);
                __stcs((float4*)&out[base + 4], o1);
            }
        }
    }
    if (pred != nullptr && tid < BM && row0 + tid < NN) {
        size_t pidx = (size_t)(pred - outbase) + (row0 + tid);
        if (pidx < out_lim) pred[row0 + tid] = (float)rowarg[tid];
    }
}

// ---------------- launch -----------------------------------------------------
extern "C" void kernel_launch(void* const* d_in, const int* in_sizes, int n_in,
                              void* d_out, int out_size) {
    const float* x  = (const float*)d_in[0];
    const int*   e1 = (const int*)d_in[1];
    const int*   e2 = (const int*)d_in[2];
    const float* W1 = (const float*)d_in[3];
    const float* b1 = (const float*)d_in[4];
    const float* W2 = (const float*)d_in[5];
    const float* b2 = (const float*)d_in[6];

    float* out = (float*)d_out;
    float* logits1 = out;
    float* logits2 = out + (size_t)NN * CH;
    float* preds   = out + 2 * (size_t)NN * CH;
    size_t out_lim = (size_t)out_size;

    float *bufA, *bufB, *bufC;
    void* cntp;
    cudaGetSymbolAddress((void**)&bufA, g_bufA);
    cudaGetSymbolAddress((void**)&bufB, g_bufB);
    cudaGetSymbolAddress((void**)&bufC, g_bufC);
    cudaGetSymbolAddress(&cntp, g_cnt);

    // dynamic smem attribute (idempotent; not a stream op)
    cudaFuncSetAttribute(gemm_softmax_kernel,
                         cudaFuncAttributeMaxDynamicSharedMemorySize, DSMEM);

    // side stream + fork/join events (created once; deterministic thereafter)
    static cudaStream_t s2 = nullptr;
    static cudaEvent_t evM = nullptr, evP1 = nullptr, evB = nullptr,
                       evG1 = nullptr;
    if (s2 == nullptr) {
        cudaStreamCreateWithFlags(&s2, cudaStreamNonBlocking);
        cudaEventCreateWithFlags(&evM, cudaEventDisableTiming);
        cudaEventCreateWithFlags(&evP1, cudaEventDisableTiming);
        cudaEventCreateWithFlags(&evB, cudaEventDisableTiming);
        cudaEventCreateWithFlags(&evG1, cudaEventDisableTiming);
    }

    int eblocks = (NE + 255) / 256;
    int gblocks = (NN + BM - 1) / BM;
    const float4* xf = (const float4*)x;
    float4* fA = (float4*)bufA;
    float4* fB = (float4*)bufB;
    float4* fC = (float4*)bufC;

    cudaMemsetAsync(cntp, 0, 2 * NN * sizeof(int));        // memset node
    cudaEventRecord(evM, 0);

    // graph-1 preprocessing on side stream (overlaps graph-0 pre + spmm)
    cudaStreamWaitEvent(s2, evM, 0);
    count_kernel<<<eblocks, 256, 0, s2>>>(e2, 1);
    scandis_kernel<<<1, 1024, 0, s2>>>(1);
    scatter_kernel<<<eblocks, 256, 0, s2>>>(e2, 1);
    cudaEventRecord(evP1, s2);

    // graph-0 preprocessing + propagation (channel-split halves, L2-resident)
    count_kernel<<<eblocks, 256>>>(e1, 0);
    scandis_kernel<<<1, 1024>>>(0);
    scatter_kernel<<<eblocks, 256>>>(e1, 0);
    spmm_kernel<<<NN, 64>>>(0, xf, fA, 0);   // pass1 half0
    spmm_kernel<<<NN, 64>>>(0, fA, fB, 0);   // pass2 half0 (bufA h0 hot)
    spmm_kernel<<<NN, 64>>>(0, xf, fA, 64);  // pass1 half1
    spmm_kernel<<<NN, 64>>>(0, fA, fB, 64);  // pass2 half1
    cudaEventRecord(evB, 0);

    // gemm1 on side stream (after its graph-1 pre chain; co-resident w/ spmm)
    cudaStreamWaitEvent(s2, evB, 0);
    gemm_softmax_kernel<<<gblocks, 256, DSMEM, s2>>>(bufB, W1, b1, logits1,
                                                     preds, out, out_lim);
    cudaEventRecord(evG1, s2);

    // conv-2 propagation + gemm on capture stream (needs graph-1 pre done)
    cudaStreamWaitEvent(0, evP1, 0);
    spmm_kernel<<<NN, 64>>>(1, xf, fA, 0);
    spmm_kernel<<<NN, 64>>>(1, fA, fC, 0);
    spmm_kernel<<<NN, 64>>>(1, xf, fA, 64);
    spmm_kernel<<<NN, 64>>>(1, fA, fC, 64);
    gemm_softmax_kernel<<<gblocks, 256, DSMEM>>>(bufC, W2, b2, logits2,
                                                 nullptr, out, out_lim);

    // join: capture stream completes only after gemm1
    cudaStreamWaitEvent(0, evG1, 0);
}